// round 8
// baseline (speedup 1.0000x reference)
#include <cuda_runtime.h>

// GLoss fused, correlation form, branch-free streaming loop.
//
// Identity (validated R6/R7):
//   G = 16*S - B - 4*(C_E + C_S + C_SE + C_SW),  B = sum w(p) d[p]^2,
//   w = 3*ry + 3*cx - ry*cx.  Full-res + pixel loss: WG*(24S - B - 4C).
//   Half-res: WGD*(16S - B - 4C) on dd = maxpool2(o) - maxpool2(t).
//
// Block = 128 threads = 512 cols (float4/thread), streams 9 row pairs
// (16 owned + 2 halo rows). Loop runs 8 uniform iterations (pairs 0..7 all
// owned); pair 8 contributes only cross terms -> peeled epilogue.
// OOB prefetch handled by clamped row offset + mask multiply (no branches);
// lane-31 edge loads are predicated ternaries (@P LDG, no divergence).

#define IMG   1024
#define HIMG  512
#define NIMG  8
#define ROWS  16
#define NPAIR 9
#define GRIDY (IMG / ROWS)            // 64
#define NBLK  (2 * GRIDY * NIMG)      // 1024

#define WG  (1.0f / 67108864.0f)      // 1/(8*8*1024*1024)
#define WGD (1.0f / 16777216.0f)      // 1/(8*8*512*512)

__device__ float g_part[NBLK];
__device__ unsigned int g_count = 0;

__device__ __forceinline__ float bw(int y, int x, int n) {
    int ry = (y == 0) + (y == n - 1);
    int cx = (x == 0) + (x == n - 1);
    return (float)(3 * ry + 3 * cx - ry * cx);
}

__device__ __forceinline__ float max4(float a, float b, float c, float d) {
    return fmaxf(fmaxf(a, b), fmaxf(c, d));
}

__global__ __launch_bounds__(128, 8) void gloss_corr(
    const float* __restrict__ img_o,
    const float* __restrict__ img_t,
    float* __restrict__ out)
{
    const int tid  = threadIdx.x;
    const int lane = tid & 31;
    const int ry0  = blockIdx.y * ROWS;
    const size_t base = (size_t)blockIdx.z * IMG * IMG;
    const int gx0 = blockIdx.x * 512 + (tid << 2);
    const int hx0 = gx0 >> 1;

    const bool isR      = (lane == 31);
    const bool edge_ld  = isR && (gx0 + 4 < IMG);
    const bool col_edge = (gx0 == 0) | (gx0 + 4 == IMG);

    const float* po_base = img_o + base + gx0;
    const float* pt_base = img_t + base + gx0;
    // safe dummy offset when not edge-loading (loads are predicated off anyway)
    const float* poe = img_o + base + (edge_ld ? gx0 + 4 : gx0);
    const float* pte = img_t + base + (edge_ld ? gx0 + 4 : gx0);
    const float2 z2 = make_float2(0.f, 0.f);

    // ---- carried diffs for current pair ----
    float4 d0, d1;
    float2 dd;
    float  eR0, eR1, eddR;

    // prologue: pair 0 (rows ry0, ry0+1 always in image)
    {
        const size_t roff = (size_t)ry0 * IMG;
        const float* po = po_base + roff;
        const float* pt = pt_base + roff;
        float4 o0 = *(const float4*)po,  o1 = *(const float4*)(po + IMG);
        float4 t0 = *(const float4*)pt,  t1 = *(const float4*)(pt + IMG);
        float2 a0 = edge_ld ? *(const float2*)(poe + roff)       : z2;
        float2 a1 = edge_ld ? *(const float2*)(poe + roff + IMG) : z2;
        float2 b0 = edge_ld ? *(const float2*)(pte + roff)       : z2;
        float2 b1 = edge_ld ? *(const float2*)(pte + roff + IMG) : z2;
        d0 = make_float4(o0.x - t0.x, o0.y - t0.y, o0.z - t0.z, o0.w - t0.w);
        d1 = make_float4(o1.x - t1.x, o1.y - t1.y, o1.z - t1.z, o1.w - t1.w);
        dd.x = max4(o0.x, o0.y, o1.x, o1.y) - max4(t0.x, t0.y, t1.x, t1.y);
        dd.y = max4(o0.z, o0.w, o1.z, o1.w) - max4(t0.z, t0.w, t1.z, t1.w);
        eR0  = a0.x - b0.x;
        eR1  = a1.x - b1.x;
        eddR = max4(a0.x, a0.y, a1.x, a1.y) - max4(b0.x, b0.y, b1.x, b1.y);
    }

    float sa = 0.f, ca0 = 0.f, ca1 = 0.f, ca2 = 0.f, ba = 0.f;
    float sh = 0.f, ch0 = 0.f, ch1 = 0.f, bh = 0.f;
    float4 dprev = make_float4(0.f, 0.f, 0.f, 0.f);
    float2 ddprev = make_float2(0.f, 0.f);
    float pnd1 = 0.f, pnddx = 0.f;

    #pragma unroll 2
    for (int j = 0; j < NPAIR - 1; j++) {        // pairs 0..7, all owned
        const int gy0 = ry0 + 2 * j;
        const int gy1 = gy0 + 1;
        const int ng  = gy0 + 2;

        // ---- 1. unconditional prefetch of pair j+1 (clamped row) ----
        const size_t roff = (size_t)(ng < IMG ? ng : IMG - 2) * IMG;
        const float  mk   = (ng < IMG) ? 1.f : 0.f;
        const float* po = po_base + roff;
        const float* pt = pt_base + roff;
        float4 no0 = *(const float4*)po;
        float4 no1 = *(const float4*)(po + IMG);
        float4 nt0 = *(const float4*)pt;
        float4 nt1 = *(const float4*)(pt + IMG);
        float2 ea0 = edge_ld ? *(const float2*)(poe + roff)       : z2;
        float2 ea1 = edge_ld ? *(const float2*)(poe + roff + IMG) : z2;
        float2 eb0 = edge_ld ? *(const float2*)(pte + roff)       : z2;
        float2 eb1 = edge_ld ? *(const float2*)(pte + roff + IMG) : z2;

        // ---- 2. +1 neighbors via shuffle ----
        float t;
        t = __shfl_down_sync(0xFFFFFFFFu, d0.x, 1); float nd0  = isR ? eR0  : t;
        t = __shfl_down_sync(0xFFFFFFFFu, d1.x, 1); float nd1  = isR ? eR1  : t;
        t = __shfl_down_sync(0xFFFFFFFFu, dd.x, 1); float nddR = isR ? eddR : t;

        // ---- 3. FMA block ----
        // cross terms with previous pair (dprev = 0 at j=0 -> no-op)
        ca0 = fmaf(dprev.x, d0.x, ca0); ca0 = fmaf(dprev.y, d0.y, ca0);   // S
        ca0 = fmaf(dprev.z, d0.z, ca0); ca0 = fmaf(dprev.w, d0.w, ca0);
        ca1 = fmaf(dprev.x, d0.y, ca1); ca1 = fmaf(dprev.y, d0.z, ca1);   // SE
        ca1 = fmaf(dprev.z, d0.w, ca1); ca1 = fmaf(dprev.w, nd0,  ca1);
        ca2 = fmaf(dprev.y, d0.x, ca2); ca2 = fmaf(dprev.z, d0.y, ca2);   // SW
        ca2 = fmaf(dprev.w, d0.z, ca2); ca2 = fmaf(pnd1,    d0.w, ca2);

        ch0 = fmaf(ddprev.x, dd.x, ch0); ch0 = fmaf(ddprev.y, dd.y, ch0); // S
        ch1 = fmaf(ddprev.x, dd.y, ch1); ch1 = fmaf(ddprev.y, nddR, ch1); // SE
        ch0 = fmaf(ddprev.y, dd.x, ch0); ch0 = fmaf(pnddx,    dd.y, ch0); // SW

        // owned terms (every loop iteration is owned)
        sa = fmaf(d0.x, d0.x, sa); sa = fmaf(d0.y, d0.y, sa);
        sa = fmaf(d0.z, d0.z, sa); sa = fmaf(d0.w, d0.w, sa);
        sa = fmaf(d1.x, d1.x, sa); sa = fmaf(d1.y, d1.y, sa);
        sa = fmaf(d1.z, d1.z, sa); sa = fmaf(d1.w, d1.w, sa);

        ca0 = fmaf(d0.x, d0.y, ca0); ca0 = fmaf(d0.y, d0.z, ca0);        // E row0
        ca0 = fmaf(d0.z, d0.w, ca0); ca0 = fmaf(d0.w, nd0,  ca0);
        ca1 = fmaf(d1.x, d1.y, ca1); ca1 = fmaf(d1.y, d1.z, ca1);        // E row1
        ca1 = fmaf(d1.z, d1.w, ca1); ca1 = fmaf(d1.w, nd1,  ca1);
        ca2 = fmaf(d0.x, d1.x, ca2); ca2 = fmaf(d0.y, d1.y, ca2);        // S pair
        ca2 = fmaf(d0.z, d1.z, ca2); ca2 = fmaf(d0.w, d1.w, ca2);
        ca0 = fmaf(d0.x, d1.y, ca0); ca0 = fmaf(d0.y, d1.z, ca0);        // SE pair
        ca0 = fmaf(d0.z, d1.w, ca0); ca0 = fmaf(d0.w, nd1,  ca0);
        ca1 = fmaf(d0.y, d1.x, ca1); ca1 = fmaf(d0.z, d1.y, ca1);        // SW pair
        ca1 = fmaf(d0.w, d1.z, ca1); ca1 = fmaf(nd0,  d1.w, ca1);

        sh  = fmaf(dd.x, dd.x, sh);  sh  = fmaf(dd.y, dd.y, sh);
        ch1 = fmaf(dd.x, dd.y, ch1); ch1 = fmaf(dd.y, nddR, ch1);        // E half

        // boundary corrections (uniformly false for interior warps)
        if (col_edge | (gy0 == 0) | (gy1 == IMG - 1)) {
            ba = fmaf(bw(gy0, gx0,     IMG) * d0.x, d0.x, ba);
            ba = fmaf(bw(gy0, gx0 + 1, IMG) * d0.y, d0.y, ba);
            ba = fmaf(bw(gy0, gx0 + 2, IMG) * d0.z, d0.z, ba);
            ba = fmaf(bw(gy0, gx0 + 3, IMG) * d0.w, d0.w, ba);
            ba = fmaf(bw(gy1, gx0,     IMG) * d1.x, d1.x, ba);
            ba = fmaf(bw(gy1, gx0 + 1, IMG) * d1.y, d1.y, ba);
            ba = fmaf(bw(gy1, gx0 + 2, IMG) * d1.z, d1.z, ba);
            ba = fmaf(bw(gy1, gx0 + 3, IMG) * d1.w, d1.w, ba);
        }
        {
            int hgy = (ry0 >> 1) + j;
            if (col_edge | (hgy == 0) | (hgy == HIMG - 1)) {
                bh = fmaf(bw(hgy, hx0,     HIMG) * dd.x, dd.x, bh);
                bh = fmaf(bw(hgy, hx0 + 1, HIMG) * dd.y, dd.y, bh);
            }
        }

        // ---- 4. convert prefetched raws -> next pair diffs (masked) ----
        float4 pd0 = make_float4((no0.x - nt0.x) * mk, (no0.y - nt0.y) * mk,
                                 (no0.z - nt0.z) * mk, (no0.w - nt0.w) * mk);
        float4 pd1 = make_float4((no1.x - nt1.x) * mk, (no1.y - nt1.y) * mk,
                                 (no1.z - nt1.z) * mk, (no1.w - nt1.w) * mk);
        float2 pdd;
        pdd.x = (max4(no0.x, no0.y, no1.x, no1.y) - max4(nt0.x, nt0.y, nt1.x, nt1.y)) * mk;
        pdd.y = (max4(no0.z, no0.w, no1.z, no1.w) - max4(nt0.z, nt0.w, nt1.z, nt1.w)) * mk;
        float peR0  = (ea0.x - eb0.x) * mk;
        float peR1  = (ea1.x - eb1.x) * mk;
        float peddR = (max4(ea0.x, ea0.y, ea1.x, ea1.y)
                     - max4(eb0.x, eb0.y, eb1.x, eb1.y)) * mk;

        // ---- 5. rotate ----
        dprev = d1; ddprev = dd; pnd1 = nd1; pnddx = nddR;
        d0 = pd0; d1 = pd1; dd = pdd;
        eR0 = peR0; eR1 = peR1; eddR = peddR;
    }

    // ---- peeled pair 8: cross terms only ----
    {
        float t;
        t = __shfl_down_sync(0xFFFFFFFFu, d0.x, 1); float nd0  = isR ? eR0  : t;
        t = __shfl_down_sync(0xFFFFFFFFu, dd.x, 1); float nddR = isR ? eddR : t;

        ca0 = fmaf(dprev.x, d0.x, ca0); ca0 = fmaf(dprev.y, d0.y, ca0);   // S
        ca0 = fmaf(dprev.z, d0.z, ca0); ca0 = fmaf(dprev.w, d0.w, ca0);
        ca1 = fmaf(dprev.x, d0.y, ca1); ca1 = fmaf(dprev.y, d0.z, ca1);   // SE
        ca1 = fmaf(dprev.z, d0.w, ca1); ca1 = fmaf(dprev.w, nd0,  ca1);
        ca2 = fmaf(dprev.y, d0.x, ca2); ca2 = fmaf(dprev.z, d0.y, ca2);   // SW
        ca2 = fmaf(dprev.w, d0.z, ca2); ca2 = fmaf(pnd1,    d0.w, ca2);

        ch0 = fmaf(ddprev.x, dd.x, ch0); ch0 = fmaf(ddprev.y, dd.y, ch0); // S
        ch1 = fmaf(ddprev.x, dd.y, ch1); ch1 = fmaf(ddprev.y, nddR, ch1); // SE
        ch0 = fmaf(ddprev.y, dd.x, ch0); ch0 = fmaf(pnddx,    dd.y, ch0); // SW
    }

    // ---------------- block reduction + last-block finalize ----------------
    __shared__ float red[4];
    __shared__ unsigned int s_last;
    float ca = ca0 + ca1 + ca2;
    float ch = ch0 + ch1;
    float val = (24.f * sa - ba - 4.f * ca) * WG
              + (16.f * sh - bh - 4.f * ch) * WGD;
    #pragma unroll
    for (int off = 16; off; off >>= 1)
        val += __shfl_down_sync(0xFFFFFFFFu, val, off);
    int warp = tid >> 5;
    if (lane == 0) red[warp] = val;
    __syncthreads();
    if (tid == 0) {
        float s = red[0] + red[1] + red[2] + red[3];
        int bid = (blockIdx.z * GRIDY + blockIdx.y) * 2 + blockIdx.x;
        g_part[bid] = s;
        __threadfence();
        unsigned old = atomicAdd(&g_count, 1u);
        s_last = (old == NBLK - 1) ? 1u : 0u;
    }
    __syncthreads();

    if (s_last) {
        double s = 0.0;
        #pragma unroll
        for (int i = tid; i < NBLK; i += 128)
            s += (double)g_part[i];
        #pragma unroll
        for (int off = 16; off; off >>= 1)
            s += __shfl_down_sync(0xFFFFFFFFu, s, off);
        __shared__ double dred[4];
        if (lane == 0) dred[warp] = s;
        __syncthreads();
        if (tid == 0) {
            out[0] = (float)(dred[0] + dred[1] + dred[2] + dred[3]);
            g_count = 0;   // reset for next graph replay
        }
    }
}

extern "C" void kernel_launch(void* const* d_in, const int* in_sizes, int n_in,
                              void* d_out, int out_size) {
    const float* img_o = (const float*)d_in[0];
    const float* img_t = (const float*)d_in[1];
    dim3 grid(2, GRIDY, NIMG);
    gloss_corr<<<grid, 128>>>(img_o, img_t, (float*)d_out);
}

// round 9
// speedup vs baseline: 1.1123x; 1.1123x over previous
#include <cuda_runtime.h>
#include <cuda_pipeline.h>

// GLoss fused, correlation form, cp.async 3-stage smem ring.
//
// Identity (validated R6/R7):
//   G = 16*S - B - 4*(C_E + C_S + C_SE + C_SW),  B = sum w(p) d[p]^2,
//   w = 3*ry + 3*cx - ry*cx.  Full-res + pixel loss: WG*(24S - B - 4C).
//   Half-res: WGD*(16S - B - 4C) on dd = maxpool2(o) - maxpool2(t).
//
// Block = 128 threads = 512 cols (float4/thread), streams 9 row pairs
// (16 owned + 2 halo). Pair j+3 is prefetched via __pipeline_memcpy_async
// into a per-thread 3-stage smem ring while the FMA block for pair j runs;
// pair j+1 is converted from smem (conflict-free LDS.128) at iteration end.
// Raw pixel values never live in registers -> occupancy stays at 8 CTAs/SM.

#define IMG   1024
#define HIMG  512
#define NIMG  8
#define ROWS  16
#define GRIDY (IMG / ROWS)            // 64
#define NBLK  (2 * GRIDY * NIMG)      // 1024

#define WG  (1.0f / 67108864.0f)      // 1/(8*8*1024*1024)
#define WGD (1.0f / 16777216.0f)      // 1/(8*8*512*512)

__device__ float g_part[NBLK];
__device__ unsigned int g_count = 0;

__device__ __forceinline__ float bw(int y, int x, int n) {
    int ry = (y == 0) + (y == n - 1);
    int cx = (x == 0) + (x == n - 1);
    return (float)(3 * ry + 3 * cx - ry * cx);
}

__device__ __forceinline__ float max4(float a, float b, float c, float d) {
    return fmaxf(fmaxf(a, b), fmaxf(c, d));
}

__global__ __launch_bounds__(128, 8) void gloss_corr(
    const float* __restrict__ img_o,
    const float* __restrict__ img_t,
    float* __restrict__ out)
{
    // 3-stage ring: [stage][slot][tid]; slot 0/1 = o rows, 2/3 = t rows. 24 KB.
    __shared__ float4 stg[3][4][128];
    __shared__ float red[4];
    __shared__ double dred[4];
    __shared__ unsigned int s_last;

    const int tid  = threadIdx.x;
    const int lane = tid & 31;
    const int ry0  = blockIdx.y * ROWS;
    const size_t base = (size_t)blockIdx.z * IMG * IMG;
    const int gx0 = blockIdx.x * 512 + (tid << 2);
    const int hx0 = gx0 >> 1;

    const bool isR      = (lane == 31);
    const bool edge_ld  = isR && (gx0 + 4 < IMG);
    const bool col_edge = (gx0 == 0) | (gx0 + 4 == IMG);
    const bool ok8      = (ry0 + 16 < IMG);      // pair 8 rows in image?

    const float* po_base = img_o + base + gx0;
    const float* pt_base = img_t + base + gx0;
    const float* poe = img_o + base + gx0 + 4;   // only deref'd when edge_ld
    const float* pte = img_t + base + gx0 + 4;
    const float2 z2 = make_float2(0.f, 0.f);

    // ---- carried diffs for current pair ----
    float4 d0, d1;
    float2 dd;
    float  eR0 = 0.f, eR1 = 0.f, eddR = 0.f;

    // prologue: pair 0 via direct LDG + convert
    {
        const size_t roff = (size_t)ry0 * IMG;
        float4 o0 = *(const float4*)(po_base + roff);
        float4 o1 = *(const float4*)(po_base + roff + IMG);
        float4 t0 = *(const float4*)(pt_base + roff);
        float4 t1 = *(const float4*)(pt_base + roff + IMG);
        d0 = make_float4(o0.x - t0.x, o0.y - t0.y, o0.z - t0.z, o0.w - t0.w);
        d1 = make_float4(o1.x - t1.x, o1.y - t1.y, o1.z - t1.z, o1.w - t1.w);
        dd.x = max4(o0.x, o0.y, o1.x, o1.y) - max4(t0.x, t0.y, t1.x, t1.y);
        dd.y = max4(o0.z, o0.w, o1.z, o1.w) - max4(t0.z, t0.w, t1.z, t1.w);
        if (edge_ld) {
            float2 a0 = *(const float2*)(poe + roff);
            float2 a1 = *(const float2*)(poe + roff + IMG);
            float2 b0 = *(const float2*)(pte + roff);
            float2 b1 = *(const float2*)(pte + roff + IMG);
            eR0  = a0.x - b0.x;
            eR1  = a1.x - b1.x;
            eddR = max4(a0.x, a0.y, a1.x, a1.y) - max4(b0.x, b0.y, b1.x, b1.y);
        }
    }

    // prologue: queue pairs 1 and 2 (always in image) as groups g0, g1
    #pragma unroll
    for (int p = 1; p <= 2; p++) {
        const size_t roff = (size_t)(ry0 + 2 * p) * IMG;
        __pipeline_memcpy_async(&stg[p % 3][0][tid], po_base + roff,       16);
        __pipeline_memcpy_async(&stg[p % 3][1][tid], po_base + roff + IMG, 16);
        __pipeline_memcpy_async(&stg[p % 3][2][tid], pt_base + roff,       16);
        __pipeline_memcpy_async(&stg[p % 3][3][tid], pt_base + roff + IMG, 16);
        __pipeline_commit();
    }

    float sa = 0.f, ca0 = 0.f, ca1 = 0.f, ca2 = 0.f, ba = 0.f;
    float sh = 0.f, ch0 = 0.f, ch1 = 0.f, bh = 0.f;
    float4 dprev = make_float4(0.f, 0.f, 0.f, 0.f);
    float2 ddprev = make_float2(0.f, 0.f);
    float pnd1 = 0.f, pnddx = 0.f;

    #pragma unroll
    for (int j = 0; j < 8; j++) {                 // pairs 0..7, all owned
        const int gy0 = ry0 + 2 * j;
        const int gy1 = gy0 + 1;

        // ---- 1. queue pair j+3 (group g_{j+2}); empty commit keeps counting ----
        {
            const int p = j + 3;
            if (p < 8 || (p == 8 && ok8)) {
                const size_t roff = (size_t)(ry0 + 2 * p) * IMG;
                __pipeline_memcpy_async(&stg[p % 3][0][tid], po_base + roff,       16);
                __pipeline_memcpy_async(&stg[p % 3][1][tid], po_base + roff + IMG, 16);
                __pipeline_memcpy_async(&stg[p % 3][2][tid], pt_base + roff,       16);
                __pipeline_memcpy_async(&stg[p % 3][3][tid], pt_base + roff + IMG, 16);
            }
            __pipeline_commit();
        }

        // edge raws for pair j+1 (lane 31; L1/L2 hits from neighbor's lines)
        float2 ea0 = z2, ea1 = z2, eb0 = z2, eb1 = z2;
        {
            const int ng = ry0 + 2 * (j + 1);
            if (edge_ld && (j < 7 || ok8)) {
                const size_t roff = (size_t)ng * IMG;
                ea0 = *(const float2*)(poe + roff);
                ea1 = *(const float2*)(poe + roff + IMG);
                eb0 = *(const float2*)(pte + roff);
                eb1 = *(const float2*)(pte + roff + IMG);
            }
        }

        // ---- 2. +1 neighbors via shuffle ----
        float t;
        t = __shfl_down_sync(0xFFFFFFFFu, d0.x, 1); float nd0  = isR ? eR0  : t;
        t = __shfl_down_sync(0xFFFFFFFFu, d1.x, 1); float nd1  = isR ? eR1  : t;
        t = __shfl_down_sync(0xFFFFFFFFu, dd.x, 1); float nddR = isR ? eddR : t;

        // ---- 3. FMA block (validated R7 math) ----
        ca0 = fmaf(dprev.x, d0.x, ca0); ca0 = fmaf(dprev.y, d0.y, ca0);   // S
        ca0 = fmaf(dprev.z, d0.z, ca0); ca0 = fmaf(dprev.w, d0.w, ca0);
        ca1 = fmaf(dprev.x, d0.y, ca1); ca1 = fmaf(dprev.y, d0.z, ca1);   // SE
        ca1 = fmaf(dprev.z, d0.w, ca1); ca1 = fmaf(dprev.w, nd0,  ca1);
        ca2 = fmaf(dprev.y, d0.x, ca2); ca2 = fmaf(dprev.z, d0.y, ca2);   // SW
        ca2 = fmaf(dprev.w, d0.z, ca2); ca2 = fmaf(pnd1,    d0.w, ca2);

        ch0 = fmaf(ddprev.x, dd.x, ch0); ch0 = fmaf(ddprev.y, dd.y, ch0); // S
        ch1 = fmaf(ddprev.x, dd.y, ch1); ch1 = fmaf(ddprev.y, nddR, ch1); // SE
        ch0 = fmaf(ddprev.y, dd.x, ch0); ch0 = fmaf(pnddx,    dd.y, ch0); // SW

        sa = fmaf(d0.x, d0.x, sa); sa = fmaf(d0.y, d0.y, sa);
        sa = fmaf(d0.z, d0.z, sa); sa = fmaf(d0.w, d0.w, sa);
        sa = fmaf(d1.x, d1.x, sa); sa = fmaf(d1.y, d1.y, sa);
        sa = fmaf(d1.z, d1.z, sa); sa = fmaf(d1.w, d1.w, sa);

        ca0 = fmaf(d0.x, d0.y, ca0); ca0 = fmaf(d0.y, d0.z, ca0);        // E row0
        ca0 = fmaf(d0.z, d0.w, ca0); ca0 = fmaf(d0.w, nd0,  ca0);
        ca1 = fmaf(d1.x, d1.y, ca1); ca1 = fmaf(d1.y, d1.z, ca1);        // E row1
        ca1 = fmaf(d1.z, d1.w, ca1); ca1 = fmaf(d1.w, nd1,  ca1);
        ca2 = fmaf(d0.x, d1.x, ca2); ca2 = fmaf(d0.y, d1.y, ca2);        // S pair
        ca2 = fmaf(d0.z, d1.z, ca2); ca2 = fmaf(d0.w, d1.w, ca2);
        ca0 = fmaf(d0.x, d1.y, ca0); ca0 = fmaf(d0.y, d1.z, ca0);        // SE pair
        ca0 = fmaf(d0.z, d1.w, ca0); ca0 = fmaf(d0.w, nd1,  ca0);
        ca1 = fmaf(d0.y, d1.x, ca1); ca1 = fmaf(d0.z, d1.y, ca1);        // SW pair
        ca1 = fmaf(d0.w, d1.z, ca1); ca1 = fmaf(nd0,  d1.w, ca1);

        sh  = fmaf(dd.x, dd.x, sh);  sh  = fmaf(dd.y, dd.y, sh);
        ch1 = fmaf(dd.x, dd.y, ch1); ch1 = fmaf(dd.y, nddR, ch1);        // E half

        if (col_edge | (gy0 == 0) | (gy1 == IMG - 1)) {
            ba = fmaf(bw(gy0, gx0,     IMG) * d0.x, d0.x, ba);
            ba = fmaf(bw(gy0, gx0 + 1, IMG) * d0.y, d0.y, ba);
            ba = fmaf(bw(gy0, gx0 + 2, IMG) * d0.z, d0.z, ba);
            ba = fmaf(bw(gy0, gx0 + 3, IMG) * d0.w, d0.w, ba);
            ba = fmaf(bw(gy1, gx0,     IMG) * d1.x, d1.x, ba);
            ba = fmaf(bw(gy1, gx0 + 1, IMG) * d1.y, d1.y, ba);
            ba = fmaf(bw(gy1, gx0 + 2, IMG) * d1.z, d1.z, ba);
            ba = fmaf(bw(gy1, gx0 + 3, IMG) * d1.w, d1.w, ba);
        }
        {
            const int hgy = (ry0 >> 1) + j;
            if (col_edge | (hgy == 0) | (hgy == HIMG - 1)) {
                bh = fmaf(bw(hgy, hx0,     HIMG) * dd.x, dd.x, bh);
                bh = fmaf(bw(hgy, hx0 + 1, HIMG) * dd.y, dd.y, bh);
            }
        }

        // ---- 4. wait for pair j+1 (group g_j) and convert from smem ----
        __pipeline_wait_prior(2);
        float4 pd0, pd1;
        float2 pdd;
        if (j < 7 || ok8) {
            const int s = (j + 1) % 3;
            float4 o0 = stg[s][0][tid], o1 = stg[s][1][tid];
            float4 t0 = stg[s][2][tid], t1 = stg[s][3][tid];
            pd0 = make_float4(o0.x - t0.x, o0.y - t0.y, o0.z - t0.z, o0.w - t0.w);
            pd1 = make_float4(o1.x - t1.x, o1.y - t1.y, o1.z - t1.z, o1.w - t1.w);
            pdd.x = max4(o0.x, o0.y, o1.x, o1.y) - max4(t0.x, t0.y, t1.x, t1.y);
            pdd.y = max4(o0.z, o0.w, o1.z, o1.w) - max4(t0.z, t0.w, t1.z, t1.w);
        } else {
            pd0 = pd1 = make_float4(0.f, 0.f, 0.f, 0.f);
            pdd = z2;
        }
        float peR0  = ea0.x - eb0.x;
        float peR1  = ea1.x - eb1.x;
        float peddR = max4(ea0.x, ea0.y, ea1.x, ea1.y)
                    - max4(eb0.x, eb0.y, eb1.x, eb1.y);

        // ---- 5. rotate ----
        dprev = d1; ddprev = dd; pnd1 = nd1; pnddx = nddR;
        d0 = pd0; d1 = pd1; dd = pdd;
        eR0 = peR0; eR1 = peR1; eddR = peddR;
    }

    // ---- peeled pair 8: cross terms only ----
    {
        float t;
        t = __shfl_down_sync(0xFFFFFFFFu, d0.x, 1); float nd0  = isR ? eR0  : t;
        t = __shfl_down_sync(0xFFFFFFFFu, dd.x, 1); float nddR = isR ? eddR : t;

        ca0 = fmaf(dprev.x, d0.x, ca0); ca0 = fmaf(dprev.y, d0.y, ca0);   // S
        ca0 = fmaf(dprev.z, d0.z, ca0); ca0 = fmaf(dprev.w, d0.w, ca0);
        ca1 = fmaf(dprev.x, d0.y, ca1); ca1 = fmaf(dprev.y, d0.z, ca1);   // SE
        ca1 = fmaf(dprev.z, d0.w, ca1); ca1 = fmaf(dprev.w, nd0,  ca1);
        ca2 = fmaf(dprev.y, d0.x, ca2); ca2 = fmaf(dprev.z, d0.y, ca2);   // SW
        ca2 = fmaf(dprev.w, d0.z, ca2); ca2 = fmaf(pnd1,    d0.w, ca2);

        ch0 = fmaf(ddprev.x, dd.x, ch0); ch0 = fmaf(ddprev.y, dd.y, ch0); // S
        ch1 = fmaf(ddprev.x, dd.y, ch1); ch1 = fmaf(ddprev.y, nddR, ch1); // SE
        ch0 = fmaf(ddprev.y, dd.x, ch0); ch0 = fmaf(pnddx,    dd.y, ch0); // SW
    }

    // ---------------- block reduction + last-block finalize ----------------
    float ca = ca0 + ca1 + ca2;
    float ch = ch0 + ch1;
    float val = (24.f * sa - ba - 4.f * ca) * WG
              + (16.f * sh - bh - 4.f * ch) * WGD;
    #pragma unroll
    for (int off = 16; off; off >>= 1)
        val += __shfl_down_sync(0xFFFFFFFFu, val, off);
    int warp = tid >> 5;
    if (lane == 0) red[warp] = val;
    __syncthreads();
    if (tid == 0) {
        float s = red[0] + red[1] + red[2] + red[3];
        int bid = (blockIdx.z * GRIDY + blockIdx.y) * 2 + blockIdx.x;
        g_part[bid] = s;
        __threadfence();
        unsigned old = atomicAdd(&g_count, 1u);
        s_last = (old == NBLK - 1) ? 1u : 0u;
    }
    __syncthreads();

    if (s_last) {
        double s = 0.0;
        #pragma unroll
        for (int i = tid; i < NBLK; i += 128)
            s += (double)g_part[i];
        #pragma unroll
        for (int off = 16; off; off >>= 1)
            s += __shfl_down_sync(0xFFFFFFFFu, s, off);
        if (lane == 0) dred[warp] = s;
        __syncthreads();
        if (tid == 0) {
            out[0] = (float)(dred[0] + dred[1] + dred[2] + dred[3]);
            g_count = 0;   // reset for next graph replay
        }
    }
}

extern "C" void kernel_launch(void* const* d_in, const int* in_sizes, int n_in,
                              void* d_out, int out_size) {
    const float* img_o = (const float*)d_in[0];
    const float* img_t = (const float*)d_in[1];
    dim3 grid(2, GRIDY, NIMG);
    gloss_corr<<<grid, 128>>>(img_o, img_t, (float*)d_out);
}

// round 10
// speedup vs baseline: 1.1555x; 1.0389x over previous
#include <cuda_runtime.h>
#include <cuda_pipeline.h>

// GLoss fused, correlation form, cp.async 4-stage ring, 32-row tiles.
//
// Identity (validated R6-R9):
//   G = 16*S - B - 4*(C_E + C_S + C_SE + C_SW),  B = sum w(p) d[p]^2,
//   w = 3*ry + 3*cx - ry*cx.  Full-res + pixel loss: WG*(24S - B - 4C).
//   Half-res: WGD*(16S - B - 4C) on dd = maxpool2(o) - maxpool2(t).
//
// Block = 128 threads = 512 cols (float4/thread), streams 17 row pairs
// (32 owned + 2 halo). Pair j+4 prefetched via cp.async into a 4-stage
// per-thread smem ring (3 iterations of cover); pair j+1 converted from
// smem at iteration end. 512 blocks -> halo traffic 6.25% (was 12.5%).

#define IMG   1024
#define HIMG  512
#define NIMG  8
#define ROWS  32
#define NITER 16                      // pairs 0..15 owned
#define GRIDY (IMG / ROWS)            // 32
#define NBLK  (2 * GRIDY * NIMG)      // 512

#define WG  (1.0f / 67108864.0f)      // 1/(8*8*1024*1024)
#define WGD (1.0f / 16777216.0f)      // 1/(8*8*512*512)

__device__ float g_part[NBLK];
__device__ unsigned int g_count = 0;

__device__ __forceinline__ float bw(int y, int x, int n) {
    int ry = (y == 0) + (y == n - 1);
    int cx = (x == 0) + (x == n - 1);
    return (float)(3 * ry + 3 * cx - ry * cx);
}

__device__ __forceinline__ float max4(float a, float b, float c, float d) {
    return fmaxf(fmaxf(a, b), fmaxf(c, d));
}

__global__ __launch_bounds__(128, 4) void gloss_corr(
    const float* __restrict__ img_o,
    const float* __restrict__ img_t,
    float* __restrict__ out)
{
    // 4-stage ring: [stage][slot][tid]; slot 0/1 = o rows, 2/3 = t rows. 32 KB.
    __shared__ float4 stg[4][4][128];
    __shared__ float red[4];
    __shared__ double dred[4];
    __shared__ unsigned int s_last;

    const int tid  = threadIdx.x;
    const int lane = tid & 31;
    const int ry0  = blockIdx.y * ROWS;
    const size_t base = (size_t)blockIdx.z * IMG * IMG;
    const int gx0 = blockIdx.x * 512 + (tid << 2);
    const int hx0 = gx0 >> 1;

    const bool isR      = (lane == 31);
    const bool edge_ld  = isR && (gx0 + 4 < IMG);
    const bool col_edge = (gx0 == 0) | (gx0 + 4 == IMG);
    const bool okL      = (ry0 + ROWS < IMG);     // last pair (16) in image?

    const float* po_base = img_o + base + gx0;
    const float* pt_base = img_t + base + gx0;
    const float* poe = img_o + base + gx0 + 4;    // only deref'd when edge_ld
    const float* pte = img_t + base + gx0 + 4;
    const float2 z2 = make_float2(0.f, 0.f);

    // ---- carried diffs for current pair ----
    float4 d0, d1;
    float2 dd;
    float  eR0 = 0.f, eR1 = 0.f, eddR = 0.f;

    // prologue: pair 0 via direct LDG + convert
    {
        const size_t roff = (size_t)ry0 * IMG;
        float4 o0 = *(const float4*)(po_base + roff);
        float4 o1 = *(const float4*)(po_base + roff + IMG);
        float4 t0 = *(const float4*)(pt_base + roff);
        float4 t1 = *(const float4*)(pt_base + roff + IMG);
        d0 = make_float4(o0.x - t0.x, o0.y - t0.y, o0.z - t0.z, o0.w - t0.w);
        d1 = make_float4(o1.x - t1.x, o1.y - t1.y, o1.z - t1.z, o1.w - t1.w);
        dd.x = max4(o0.x, o0.y, o1.x, o1.y) - max4(t0.x, t0.y, t1.x, t1.y);
        dd.y = max4(o0.z, o0.w, o1.z, o1.w) - max4(t0.z, t0.w, t1.z, t1.w);
        if (edge_ld) {
            float2 a0 = *(const float2*)(poe + roff);
            float2 a1 = *(const float2*)(poe + roff + IMG);
            float2 b0 = *(const float2*)(pte + roff);
            float2 b1 = *(const float2*)(pte + roff + IMG);
            eR0  = a0.x - b0.x;
            eR1  = a1.x - b1.x;
            eddR = max4(a0.x, a0.y, a1.x, a1.y) - max4(b0.x, b0.y, b1.x, b1.y);
        }
    }

    // prologue: queue pairs 1..3 (always in image) as groups g0..g2
    #pragma unroll
    for (int p = 1; p <= 3; p++) {
        const size_t roff = (size_t)(ry0 + 2 * p) * IMG;
        __pipeline_memcpy_async(&stg[p & 3][0][tid], po_base + roff,       16);
        __pipeline_memcpy_async(&stg[p & 3][1][tid], po_base + roff + IMG, 16);
        __pipeline_memcpy_async(&stg[p & 3][2][tid], pt_base + roff,       16);
        __pipeline_memcpy_async(&stg[p & 3][3][tid], pt_base + roff + IMG, 16);
        __pipeline_commit();
    }

    float sa = 0.f, ca0 = 0.f, ca1 = 0.f, ca2 = 0.f, ba = 0.f;
    float sh = 0.f, ch0 = 0.f, ch1 = 0.f, bh = 0.f;
    float4 dprev = make_float4(0.f, 0.f, 0.f, 0.f);
    float2 ddprev = make_float2(0.f, 0.f);
    float pnd1 = 0.f, pnddx = 0.f;

    #pragma unroll 4
    for (int j = 0; j < NITER; j++) {             // pairs 0..15, all owned
        const int gy0 = ry0 + 2 * j;
        const int gy1 = gy0 + 1;

        // ---- 1. queue pair j+4 (empty commit keeps group counting uniform) ----
        {
            const int p = j + 4;
            if (p < NITER || (p == NITER && okL)) {
                const size_t roff = (size_t)(ry0 + 2 * p) * IMG;
                __pipeline_memcpy_async(&stg[p & 3][0][tid], po_base + roff,       16);
                __pipeline_memcpy_async(&stg[p & 3][1][tid], po_base + roff + IMG, 16);
                __pipeline_memcpy_async(&stg[p & 3][2][tid], pt_base + roff,       16);
                __pipeline_memcpy_async(&stg[p & 3][3][tid], pt_base + roff + IMG, 16);
            }
            __pipeline_commit();
        }

        // edge raws for pair j+1 (lane 31; mostly L1/L2 hits)
        float2 ea0 = z2, ea1 = z2, eb0 = z2, eb1 = z2;
        {
            const int ng = ry0 + 2 * (j + 1);
            if (edge_ld && (j < NITER - 1 || okL)) {
                const size_t roff = (size_t)ng * IMG;
                ea0 = *(const float2*)(poe + roff);
                ea1 = *(const float2*)(poe + roff + IMG);
                eb0 = *(const float2*)(pte + roff);
                eb1 = *(const float2*)(pte + roff + IMG);
            }
        }

        // ---- 2. +1 neighbors via shuffle ----
        float t;
        t = __shfl_down_sync(0xFFFFFFFFu, d0.x, 1); float nd0  = isR ? eR0  : t;
        t = __shfl_down_sync(0xFFFFFFFFu, d1.x, 1); float nd1  = isR ? eR1  : t;
        t = __shfl_down_sync(0xFFFFFFFFu, dd.x, 1); float nddR = isR ? eddR : t;

        // ---- 3. FMA block (validated math) ----
        ca0 = fmaf(dprev.x, d0.x, ca0); ca0 = fmaf(dprev.y, d0.y, ca0);   // S
        ca0 = fmaf(dprev.z, d0.z, ca0); ca0 = fmaf(dprev.w, d0.w, ca0);
        ca1 = fmaf(dprev.x, d0.y, ca1); ca1 = fmaf(dprev.y, d0.z, ca1);   // SE
        ca1 = fmaf(dprev.z, d0.w, ca1); ca1 = fmaf(dprev.w, nd0,  ca1);
        ca2 = fmaf(dprev.y, d0.x, ca2); ca2 = fmaf(dprev.z, d0.y, ca2);   // SW
        ca2 = fmaf(dprev.w, d0.z, ca2); ca2 = fmaf(pnd1,    d0.w, ca2);

        ch0 = fmaf(ddprev.x, dd.x, ch0); ch0 = fmaf(ddprev.y, dd.y, ch0); // S
        ch1 = fmaf(ddprev.x, dd.y, ch1); ch1 = fmaf(ddprev.y, nddR, ch1); // SE
        ch0 = fmaf(ddprev.y, dd.x, ch0); ch0 = fmaf(pnddx,    dd.y, ch0); // SW

        sa = fmaf(d0.x, d0.x, sa); sa = fmaf(d0.y, d0.y, sa);
        sa = fmaf(d0.z, d0.z, sa); sa = fmaf(d0.w, d0.w, sa);
        sa = fmaf(d1.x, d1.x, sa); sa = fmaf(d1.y, d1.y, sa);
        sa = fmaf(d1.z, d1.z, sa); sa = fmaf(d1.w, d1.w, sa);

        ca0 = fmaf(d0.x, d0.y, ca0); ca0 = fmaf(d0.y, d0.z, ca0);        // E row0
        ca0 = fmaf(d0.z, d0.w, ca0); ca0 = fmaf(d0.w, nd0,  ca0);
        ca1 = fmaf(d1.x, d1.y, ca1); ca1 = fmaf(d1.y, d1.z, ca1);        // E row1
        ca1 = fmaf(d1.z, d1.w, ca1); ca1 = fmaf(d1.w, nd1,  ca1);
        ca2 = fmaf(d0.x, d1.x, ca2); ca2 = fmaf(d0.y, d1.y, ca2);        // S pair
        ca2 = fmaf(d0.z, d1.z, ca2); ca2 = fmaf(d0.w, d1.w, ca2);
        ca0 = fmaf(d0.x, d1.y, ca0); ca0 = fmaf(d0.y, d1.z, ca0);        // SE pair
        ca0 = fmaf(d0.z, d1.w, ca0); ca0 = fmaf(d0.w, nd1,  ca0);
        ca1 = fmaf(d0.y, d1.x, ca1); ca1 = fmaf(d0.z, d1.y, ca1);        // SW pair
        ca1 = fmaf(d0.w, d1.z, ca1); ca1 = fmaf(nd0,  d1.w, ca1);

        sh  = fmaf(dd.x, dd.x, sh);  sh  = fmaf(dd.y, dd.y, sh);
        ch1 = fmaf(dd.x, dd.y, ch1); ch1 = fmaf(dd.y, nddR, ch1);        // E half

        if (col_edge | (gy0 == 0) | (gy1 == IMG - 1)) {
            ba = fmaf(bw(gy0, gx0,     IMG) * d0.x, d0.x, ba);
            ba = fmaf(bw(gy0, gx0 + 1, IMG) * d0.y, d0.y, ba);
            ba = fmaf(bw(gy0, gx0 + 2, IMG) * d0.z, d0.z, ba);
            ba = fmaf(bw(gy0, gx0 + 3, IMG) * d0.w, d0.w, ba);
            ba = fmaf(bw(gy1, gx0,     IMG) * d1.x, d1.x, ba);
            ba = fmaf(bw(gy1, gx0 + 1, IMG) * d1.y, d1.y, ba);
            ba = fmaf(bw(gy1, gx0 + 2, IMG) * d1.z, d1.z, ba);
            ba = fmaf(bw(gy1, gx0 + 3, IMG) * d1.w, d1.w, ba);
        }
        {
            const int hgy = (ry0 >> 1) + j;
            if (col_edge | (hgy == 0) | (hgy == HIMG - 1)) {
                bh = fmaf(bw(hgy, hx0,     HIMG) * dd.x, dd.x, bh);
                bh = fmaf(bw(hgy, hx0 + 1, HIMG) * dd.y, dd.y, bh);
            }
        }

        // ---- 4. wait for pair j+1 and convert from smem ----
        __pipeline_wait_prior(3);
        float4 pd0, pd1;
        float2 pdd;
        if (j < NITER - 1 || okL) {
            const int s = (j + 1) & 3;
            float4 o0 = stg[s][0][tid], o1 = stg[s][1][tid];
            float4 t0 = stg[s][2][tid], t1 = stg[s][3][tid];
            pd0 = make_float4(o0.x - t0.x, o0.y - t0.y, o0.z - t0.z, o0.w - t0.w);
            pd1 = make_float4(o1.x - t1.x, o1.y - t1.y, o1.z - t1.z, o1.w - t1.w);
            pdd.x = max4(o0.x, o0.y, o1.x, o1.y) - max4(t0.x, t0.y, t1.x, t1.y);
            pdd.y = max4(o0.z, o0.w, o1.z, o1.w) - max4(t0.z, t0.w, t1.z, t1.w);
        } else {
            pd0 = pd1 = make_float4(0.f, 0.f, 0.f, 0.f);
            pdd = z2;
        }
        float peR0  = ea0.x - eb0.x;
        float peR1  = ea1.x - eb1.x;
        float peddR = max4(ea0.x, ea0.y, ea1.x, ea1.y)
                    - max4(eb0.x, eb0.y, eb1.x, eb1.y);

        // ---- 5. rotate ----
        dprev = d1; ddprev = dd; pnd1 = nd1; pnddx = nddR;
        d0 = pd0; d1 = pd1; dd = pdd;
        eR0 = peR0; eR1 = peR1; eddR = peddR;
    }

    // ---- peeled last pair: cross terms only ----
    {
        float t;
        t = __shfl_down_sync(0xFFFFFFFFu, d0.x, 1); float nd0  = isR ? eR0  : t;
        t = __shfl_down_sync(0xFFFFFFFFu, dd.x, 1); float nddR = isR ? eddR : t;

        ca0 = fmaf(dprev.x, d0.x, ca0); ca0 = fmaf(dprev.y, d0.y, ca0);   // S
        ca0 = fmaf(dprev.z, d0.z, ca0); ca0 = fmaf(dprev.w, d0.w, ca0);
        ca1 = fmaf(dprev.x, d0.y, ca1); ca1 = fmaf(dprev.y, d0.z, ca1);   // SE
        ca1 = fmaf(dprev.z, d0.w, ca1); ca1 = fmaf(dprev.w, nd0,  ca1);
        ca2 = fmaf(dprev.y, d0.x, ca2); ca2 = fmaf(dprev.z, d0.y, ca2);   // SW
        ca2 = fmaf(dprev.w, d0.z, ca2); ca2 = fmaf(pnd1,    d0.w, ca2);

        ch0 = fmaf(ddprev.x, dd.x, ch0); ch0 = fmaf(ddprev.y, dd.y, ch0); // S
        ch1 = fmaf(ddprev.x, dd.y, ch1); ch1 = fmaf(ddprev.y, nddR, ch1); // SE
        ch0 = fmaf(ddprev.y, dd.x, ch0); ch0 = fmaf(pnddx,    dd.y, ch0); // SW
    }

    // ---------------- block reduction + last-block finalize ----------------
    float ca = ca0 + ca1 + ca2;
    float ch = ch0 + ch1;
    float val = (24.f * sa - ba - 4.f * ca) * WG
              + (16.f * sh - bh - 4.f * ch) * WGD;
    #pragma unroll
    for (int off = 16; off; off >>= 1)
        val += __shfl_down_sync(0xFFFFFFFFu, val, off);
    int warp = tid >> 5;
    if (lane == 0) red[warp] = val;
    __syncthreads();
    if (tid == 0) {
        float s = red[0] + red[1] + red[2] + red[3];
        int bid = (blockIdx.z * GRIDY + blockIdx.y) * 2 + blockIdx.x;
        g_part[bid] = s;
        __threadfence();
        unsigned old = atomicAdd(&g_count, 1u);
        s_last = (old == NBLK - 1) ? 1u : 0u;
    }
    __syncthreads();

    if (s_last) {
        double s = 0.0;
        #pragma unroll
        for (int i = tid; i < NBLK; i += 128)
            s += (double)g_part[i];
        #pragma unroll
        for (int off = 16; off; off >>= 1)
            s += __shfl_down_sync(0xFFFFFFFFu, s, off);
        if (lane == 0) dred[warp] = s;
        __syncthreads();
        if (tid == 0) {
            out[0] = (float)(dred[0] + dred[1] + dred[2] + dred[3]);
            g_count = 0;   // reset for next graph replay
        }
    }
}

extern "C" void kernel_launch(void* const* d_in, const int* in_sizes, int n_in,
                              void* d_out, int out_size) {
    const float* img_o = (const float*)d_in[0];
    const float* img_t = (const float*)d_in[1];
    dim3 grid(2, GRIDY, NIMG);
    gloss_corr<<<grid, 128>>>(img_o, img_t, (float*)d_out);
}